// round 12
// baseline (speedup 1.0000x reference)
#include <cuda_runtime.h>
#include <cuda_bf16.h>
#include <stdint.h>

#define TN 2000
#define UN 50000
#define TF 16
#define OUTC (TF + 36)
#define NF 40                   // B rows: 0..35 emb, 36 count, 37..39 zero
#define KPAD 50176              // mult of 64
#define KT2 64                  // K per pipeline stage
#define NST_TOT (KPAD / KT2)    // 784
#define MB 128                  // M per CTA (4 warps x m32)
#define NMB 16
#define TPAD (NMB * MB)         // 2048
#define NSPLIT 18               // grid = 288 CTAs ~ 2/SM
#define NTHR 128
#define ASTR 72                              // A row stride (ints): conflict-free
#define ASTAGE_B (128 * ASTR * 4)            // 36864 B
#define BSTR 40                              // B row stride (words): conflict-free
#define BSTAGE_B (NF * BSTR * 4)             // 6400 B
#define TAB_FLOATS 5628                      // 6 tables x 6 cols (222+27+373+283+26+7 rows)
#define TAB_B (TAB_FLOATS * 4)               // 22512 B
#define SMEM_TOTAL (2 * (ASTAGE_B + BSTAGE_B) + TAB_B)   // 109040 B

// ---------------- device scratch (static) ----------------
__device__ float g_part[(size_t)NSPLIT * TPAD * NF];

__device__ __forceinline__ uint32_t smem_u32(const void* p) {
    uint32_t a;
    asm("{ .reg .u64 t; cvta.to.shared.u64 t, %1; cvt.u32.u64 %0, t; }" : "=r"(a) : "l"(p));
    return a;
}
__device__ __forceinline__ void mma16816(float* c, uint32_t a0, uint32_t a1,
                                         uint32_t a2, uint32_t a3,
                                         uint32_t b0, uint32_t b1) {
    asm volatile("mma.sync.aligned.m16n8k16.row.col.f32.bf16.bf16.f32 "
                 "{%0,%1,%2,%3}, {%4,%5,%6,%7}, {%8,%9}, {%0,%1,%2,%3};"
                 : "+f"(c[0]), "+f"(c[1]), "+f"(c[2]), "+f"(c[3])
                 : "r"(a0), "r"(a1), "r"(a2), "r"(a3), "r"(b0), "r"(b1));
}
__device__ __forceinline__ uint32_t pk(int2 m) {
    return (uint32_t)(m.x + (m.y << 16)) * 0x3F80u;
}

__constant__ int c_offs[6] = {0, 1332, 1494, 3732, 5430, 5586};
__constant__ int c_cnts[6] = {1332, 162, 2238, 1698, 156, 42};

// ---------------- A-tile cp.async ----------------
__device__ __forceinline__ void issue_stage(uint32_t smb, int s, int k0,
                                            const int* __restrict__ tum,
                                            int t0, int tid) {
    uint32_t aB = smb + s * ASTAGE_B;
#pragma unroll
    for (int i = 0; i < 16; i++) {
        int q = tid + i * NTHR;
        int r = q >> 4;
        int c = (q & 15) << 2;
        uint32_t dst = aB + (uint32_t)r * (ASTR * 4) + (uint32_t)(q & 15) * 16u;
        const int* src = tum + (size_t)(t0 + r) * UN + (k0 + c);
        uint32_t sz = ((t0 + r) < TN && (k0 + c) < UN) ? 16u : 0u;
        asm volatile("cp.async.cg.shared.global [%0], [%1], 16, %2;"
                     :: "r"(dst), "l"(src), "r"(sz));
    }
}

// ---------------- B-tile build: 2 threads per user, tables from smem ----------------
// Paired-word layout: user ul -> bf16 column wp*2+d, wp = perm(ul>>1), d = ul&1.
// compute_stage reads word w=8a+2c+e of row r as elements k=16a+2c+8e (pair) -- matches.
__device__ __forceinline__ void build_B(char* sm, int s, int k0,
                                        const unsigned* __restrict__ us,
                                        int is64, int tid, const float* sTab) {
    __nv_bfloat16* bB = (__nv_bfloat16*)(sm + 2 * ASTAGE_B + s * BSTAGE_B);
    const int ul = tid >> 1, h = tid & 1;
    const int u = k0 + ul;
    const int pr = ul >> 1, d = ul & 1;
    const int wp = ((pr >> 3) << 3) + ((pr & 3) << 1) + ((pr >> 2) & 1);
    __nv_bfloat16* base = bB + wp * 2 + d;       // row stride = 80 bf16
    if (u < UN) {
#pragma unroll
        for (int i = 0; i < 3; i++) {
            const int ti = 3 * h + i;
            unsigned ix = us[(unsigned)(u * 6 + ti) << is64];
            const float* row = sTab + c_offs[ti] + (size_t)ix * 6;
            float2 r0 = *(const float2*)row;
            float2 r1 = *(const float2*)(row + 2);
            float2 r2 = *(const float2*)(row + 4);
            base[(ti * 6 + 0) * 80] = __float2bfloat16(r0.x);
            base[(ti * 6 + 1) * 80] = __float2bfloat16(r0.y);
            base[(ti * 6 + 2) * 80] = __float2bfloat16(r1.x);
            base[(ti * 6 + 3) * 80] = __float2bfloat16(r1.y);
            base[(ti * 6 + 4) * 80] = __float2bfloat16(r2.x);
            base[(ti * 6 + 5) * 80] = __float2bfloat16(r2.y);
        }
        if (h == 0) base[36 * 80] = __float2bfloat16(1.0f);   // count row
    } else {
        __nv_bfloat16 z = __float2bfloat16(0.0f);
#pragma unroll
        for (int i = 0; i < 3; i++) {
            const int ti = 3 * h + i;
#pragma unroll
            for (int j = 0; j < 6; j++) base[(ti * 6 + j) * 80] = z;
        }
        if (h == 0) base[36 * 80] = z;
    }
}

__device__ __forceinline__ void compute_stage(const char* sm, int s, float acc[2][5][4],
                                              int w, int g, int cc) {
    const int* aP = (const int*)(sm + s * ASTAGE_B);
    const uint32_t* bP = (const uint32_t*)(sm + 2 * ASTAGE_B + s * BSTAGE_B);
    const int rowA = (32 * w + g) * ASTR + 2 * cc;
#pragma unroll
    for (int ks = 0; ks < 4; ks++) {
        uint32_t bf[10];
        const uint32_t* bb = bP + g * BSTR + ks * 8 + cc * 2;
#pragma unroll
        for (int nb = 0; nb < 5; nb++) {
            uint2 v = *(const uint2*)(bb + nb * 8 * BSTR);
            bf[2 * nb] = v.x;
            bf[2 * nb + 1] = v.y;
        }
#pragma unroll
        for (int mh = 0; mh < 2; mh++) {
            const int* p0 = aP + rowA + mh * 16 * ASTR + 16 * ks;
            int2 x0 = *(const int2*)(p0);
            int2 x2 = *(const int2*)(p0 + 8);
            int2 x1 = *(const int2*)(p0 + 8 * ASTR);
            int2 x3 = *(const int2*)(p0 + 8 * ASTR + 8);
            uint32_t a0 = pk(x0), a1 = pk(x1), a2 = pk(x2), a3 = pk(x3);
#pragma unroll
            for (int nb = 0; nb < 5; nb++)
                mma16816(acc[mh][nb], a0, a1, a2, a3, bf[2 * nb], bf[2 * nb + 1]);
        }
    }
}

__global__ void __launch_bounds__(NTHR, 2) accum_kernel(
        const int* __restrict__ tum,
        const unsigned int* __restrict__ us,
        const float* __restrict__ e0, const float* __restrict__ e1,
        const float* __restrict__ e2, const float* __restrict__ e3,
        const float* __restrict__ e4, const float* __restrict__ e5) {
    extern __shared__ char sm[];
    __shared__ int s_is64;
    const int tid = threadIdx.x;
    const int w = tid >> 5, lane = tid & 31;
    const int g = lane >> 2, cc = lane & 3;
    const int mb = blockIdx.x & (NMB - 1);
    const int sp = blockIdx.x >> 4;
    const int t0 = mb * MB;
    const uint32_t smb = smem_u32(sm);
    float* sTab = (float*)(sm + 2 * ASTAGE_B + 2 * BSTAGE_B);

    const int J = (NST_TOT - sp + NSPLIT - 1) / NSPLIT;

    // ---- prologue: A0 in flight immediately ----
    issue_stage(smb, 0, sp * KT2, tum, t0, tid);
    asm volatile("cp.async.commit_group;");

    // ---- stage tables into smem, probe index width, zero B rows 37-39 ----
    if (tid == 0) {
        unsigned probe = 0;
#pragma unroll
        for (int ww = 1; ww < 32; ww += 2) probe |= us[ww];
        s_is64 = (probe == 0u);   // int64 serialization -> zero high words
    }
    {
        const float* srcs[6] = {e0, e1, e2, e3, e4, e5};
#pragma unroll
        for (int i = 0; i < 6; i++)
            for (int q = tid; q < c_cnts[i]; q += NTHR) sTab[c_offs[i] + q] = srcs[i][q];
        uint32_t* b0w = (uint32_t*)(sm + 2 * ASTAGE_B);
        uint32_t* b1w = (uint32_t*)(sm + 2 * ASTAGE_B + BSTAGE_B);
        if (tid < 3 * BSTR) {
            b0w[37 * BSTR + tid] = 0;
            b1w[37 * BSTR + tid] = 0;
        }
    }
    __syncthreads();
    const int is64 = s_is64;

    build_B(sm, 0, sp * KT2, us, is64, tid, sTab);

    float acc[2][5][4];
#pragma unroll
    for (int mh = 0; mh < 2; mh++)
#pragma unroll
        for (int nb = 0; nb < 5; nb++)
#pragma unroll
            for (int q = 0; q < 4; q++) acc[mh][nb][q] = 0.0f;

    for (int j = 0; j < J; j++) {
        __syncthreads();   // buffer (j+1)&1 free: compute(j-1) done by all warps
        if (j + 1 < J) {
            const int k1 = (sp + (j + 1) * NSPLIT) * KT2;
            issue_stage(smb, (j + 1) & 1, k1, tum, t0, tid);
            asm volatile("cp.async.commit_group;");
            build_B(sm, (j + 1) & 1, k1, us, is64, tid, sTab);  // overlaps A_j wait
            asm volatile("cp.async.wait_group 1;");   // in-order: group j retired
        } else {
            asm volatile("cp.async.wait_group 0;");
        }
        __syncthreads();
        compute_stage(sm, j & 1, acc, w, g, cc);
    }

    float* part = g_part + (size_t)sp * TPAD * NF;
#pragma unroll
    for (int mh = 0; mh < 2; mh++) {
        int tA = t0 + 32 * w + 16 * mh + g;
#pragma unroll
        for (int nb = 0; nb < 5; nb++) {
            int col = nb * 8 + 2 * cc;
            if (tA < TN)
                *(float2*)(&part[(size_t)tA * NF + col]) =
                    make_float2(acc[mh][nb][0], acc[mh][nb][1]);
            if (tA + 8 < TN)
                *(float2*)(&part[(size_t)(tA + 8) * NF + col]) =
                    make_float2(acc[mh][nb][2], acc[mh][nb][3]);
        }
    }
}

// ---------------- finalize: one 64-thread block per team ----------------
__global__ void __launch_bounds__(64) finalize_kernel(const float* __restrict__ T_static,
                                                      float* __restrict__ out) {
    __shared__ float s_cnt;
    const int t = blockIdx.x;
    const int tid = threadIdx.x;
    float s = 0.0f;
    if (tid < NF) {
        const float* base = g_part + (size_t)t * NF + tid;
#pragma unroll
        for (int k = 0; k < NSPLIT; k++) s += base[(size_t)k * (TPAD * NF)];
        if (tid == 36) s_cnt = s;
    }
    __syncthreads();
    if (tid < 36) out[t * OUTC + TF + tid] = s / s_cnt;
    else if (tid >= 40 && tid < 40 + TF) {
        int c = tid - 40;
        out[t * OUTC + c] = T_static[t * TF + c];
    }
}

extern "C" void kernel_launch(void* const* d_in, const int* in_sizes, int n_in,
                              void* d_out, int out_size) {
    const float* T_static = (const float*)d_in[0];
    const unsigned int* us = (const unsigned int*)d_in[1];
    const int* tum = (const int*)d_in[2];
    const float* e0 = (const float*)d_in[3];
    const float* e1 = (const float*)d_in[4];
    const float* e2 = (const float*)d_in[5];
    const float* e3 = (const float*)d_in[6];
    const float* e4 = (const float*)d_in[7];
    const float* e5 = (const float*)d_in[8];
    float* out = (float*)d_out;

    cudaFuncSetAttribute(accum_kernel, cudaFuncAttributeMaxDynamicSharedMemorySize,
                         SMEM_TOTAL);
    accum_kernel<<<NMB * NSPLIT, NTHR, SMEM_TOTAL>>>(tum, us, e0, e1, e2, e3, e4, e5);
    finalize_kernel<<<TN, 64>>>(T_static, out);
}